// round 9
// baseline (speedup 1.0000x reference)
#include <cuda_runtime.h>

#define EPS 1e-6f

static constexpr int B_ = 64;
static constexpr int T_ = 8000;
static constexpr int M_ = 80;
static constexpr int MQ  = M_ / 4;       // 20 float4 lanes per row
static constexpr int MQP = MQ + 1;       // padded SMEM row (bank-conflict dodge)
static constexpr int CL = 100;           // timesteps per chunk
static constexpr int NC = T_ / CL;       // 80 chunks
static constexpr int SS = 10;            // subchunks per chunk
static constexpr int L  = CL / SS;       // 10 steps per subchunk
static constexpr int SCAN_T = MQ * SS;   // 200 scan threads
static constexpr int NTH = 256;
static constexpr int SLANES = B_ * M_;   // 5120 scalar lanes

// Scratch (no cudaMalloc allowed). Scalar view: [NC][B_*M_] floats.
__device__ float4 g_part[NC * B_ * MQ];
__device__ float4 g_carry[NC * B_ * MQ];

// Single-instruction MUFU wrappers.
__device__ __forceinline__ float fast_lg2(float v) {
    float r; asm("lg2.approx.f32 %0, %1;" : "=f"(r) : "f"(v)); return r;
}
__device__ __forceinline__ float fast_ex2(float v) {
    float r; asm("ex2.approx.f32 %0, %1;" : "=f"(r) : "f"(v)); return r;
}

// out = (x*(m+eps)^(-alpha) + delta)^r - delta^r, division-free (4 MUFU ops)
__device__ __forceinline__ float pcen_out(float xv, float mv, float nalpha,
                                          float delta, float r, float dr) {
    float l   = fast_lg2(mv + EPS);
    float den = fast_ex2(nalpha * l);
    float y   = fmaf(xv, den, delta);
    return fast_ex2(r * fast_lg2(y)) - dr;
}

// ---------------------------------------------------------------------------
// Pass 1: block per (chunk c, batch b). Stage 32KB x-tile with perfectly
// coalesced sequential loads, zero-init subchunk scans from SMEM, in-block
// combine, write block partial (320B).
// ---------------------------------------------------------------------------
__global__ void __launch_bounds__(NTH) pcen_pass1(
        const float4* __restrict__ x, const float* __restrict__ log_s) {
    __shared__ float4 sm_tile[CL * MQP];
    __shared__ float4 sm_ep[SS * MQ];

    const int bid = blockIdx.x;
    const int c   = bid / B_;
    const int b   = bid % B_;
    const int tid = threadIdx.x;

    const float4* xp = x + ((size_t)b * T_ + (size_t)c * CL) * MQ;
    for (int i = tid; i < CL * MQ; i += NTH) {
        int row = i / MQ, col = i % MQ;
        sm_tile[row * MQP + col] = __ldg(xp + i);
    }
    __syncthreads();

    const int mq = tid % MQ;
    const int ss = tid / MQ;
    float4 o4;
    if (tid < SCAN_T) {
        int m0 = mq * 4;
        float4 s4;
        s4.x = __expf(log_s[m0 + 0]); s4.y = __expf(log_s[m0 + 1]);
        s4.z = __expf(log_s[m0 + 2]); s4.w = __expf(log_s[m0 + 3]);
        o4.x = 1.0f - s4.x; o4.y = 1.0f - s4.y;
        o4.z = 1.0f - s4.z; o4.w = 1.0f - s4.w;

        float4 e = make_float4(0.f, 0.f, 0.f, 0.f);
#pragma unroll
        for (int j = 0; j < L; j++) {
            float4 xv = sm_tile[(ss * L + j) * MQP + mq];
            e.x = fmaf(o4.x, e.x, s4.x * xv.x);
            e.y = fmaf(o4.y, e.y, s4.y * xv.y);
            e.z = fmaf(o4.z, e.z, s4.z * xv.z);
            e.w = fmaf(o4.w, e.w, s4.w * xv.w);
        }
        sm_ep[ss * MQ + mq] = e;
    }
    __syncthreads();

    if (tid < MQ) {
        float4 dL = make_float4(1.f, 1.f, 1.f, 1.f);
#pragma unroll
        for (int k = 0; k < L; k++) {
            dL.x *= o4.x; dL.y *= o4.y; dL.z *= o4.z; dL.w *= o4.w;
        }
        float4 p = make_float4(0.f, 0.f, 0.f, 0.f);
#pragma unroll
        for (int k = 0; k < SS; k++) {
            float4 e = sm_ep[k * MQ + mq];
            p.x = fmaf(dL.x, p.x, e.x);
            p.y = fmaf(dL.y, p.y, e.y);
            p.z = fmaf(dL.z, p.z, e.z);
            p.w = fmaf(dL.w, p.w, e.w);
        }
        g_part[((size_t)c * B_ + b) * MQ + mq] = p;
    }
}

// ---------------------------------------------------------------------------
// Pass 2: per-lane serial combine staged through SMEM (R5 scheme, NC=80).
// carry_{c+1} = partial_c + (1-s)^CL * carry_c ; g_carry holds carry-IN.
// ---------------------------------------------------------------------------
static constexpr int LPB = 64;
__global__ void __launch_bounds__(NTH) pcen_pass2(
        const float* __restrict__ log_s) {
    __shared__ float sm[NC][LPB];  // 20480 B
    const int lane0 = blockIdx.x * LPB;
    const float* gp = reinterpret_cast<const float*>(g_part);
    float*       gc = reinterpret_cast<float*>(g_carry);

    for (int i = threadIdx.x; i < NC * LPB; i += NTH) {
        int c = i / LPB, l = i % LPB;
        sm[c][l] = gp[(size_t)c * SLANES + lane0 + l];
    }
    __syncthreads();

    if (threadIdx.x < LPB) {
        int l = threadIdx.x;
        int m = (lane0 + l) % M_;
        float s   = __expf(log_s[m]);
        float oms = 1.0f - s;
        float dL = 1.0f;
#pragma unroll
        for (int i = 0; i < L; i++) dL *= oms;
        float dC = 1.0f;
#pragma unroll
        for (int i = 0; i < SS; i++) dC *= dL;

        float carry = 0.0f;
#pragma unroll 5
        for (int c = 0; c < NC; c++) {
            float p = sm[c][l];
            sm[c][l] = carry;              // carry-IN for chunk c
            carry = fmaf(dC, carry, p);
        }
    }
    __syncthreads();

    for (int i = threadIdx.x; i < NC * LPB; i += NTH) {
        int c = i / LPB, l = i % LPB;
        gc[(size_t)c * SLANES + lane0 + l] = sm[c][l];
    }
}

// ---------------------------------------------------------------------------
// Pass 3: block per (c,b). Params precomputed once into SMEM; stage tile
// coalesced; zero-init subchunk scans; in-block exclusive combine; exact-carry
// rescan + epilogue; coalesced-ish direct stores.
// ---------------------------------------------------------------------------
__global__ void __launch_bounds__(NTH) pcen_pass3(
        const float4* __restrict__ x,
        const float* __restrict__ log_s,
        const float* __restrict__ log_alpha,
        const float* __restrict__ log_delta,
        const float* __restrict__ log_r,
        float4* __restrict__ out) {
    __shared__ float4 sm_tile[CL * MQP];
    __shared__ float4 sm_ep[SS * MQ];
    __shared__ float sp_s[M_], sp_o[M_], sp_na[M_], sp_d[M_], sp_r[M_], sp_dr[M_];

    const int bid = blockIdx.x;
    const int c   = bid / B_;
    const int b   = bid % B_;
    const int tid = threadIdx.x;

    // Per-mel params computed once per block (80 threads, not 200x).
    if (tid < M_) {
        float ls = log_s[tid], la = log_alpha[tid];
        float ld = log_delta[tid], lr = log_r[tid];
        float s = __expf(ls);
        float r = __expf(lr);
        sp_s[tid]  = s;
        sp_o[tid]  = 1.0f - s;
        sp_na[tid] = -__expf(la);
        sp_d[tid]  = __expf(ld);
        sp_r[tid]  = r;
        sp_dr[tid] = __expf(r * ld);
    }

    const float4* xp = x + ((size_t)b * T_ + (size_t)c * CL) * MQ;
    for (int i = tid; i < CL * MQ; i += NTH) {
        int row = i / MQ, col = i % MQ;
        sm_tile[row * MQP + col] = __ldg(xp + i);
    }
    __syncthreads();

    const int mq = tid % MQ;
    const int ss = tid / MQ;
    float4 s4, o4;
    if (tid < SCAN_T) {
        int m0 = mq * 4;
        s4.x = sp_s[m0 + 0]; s4.y = sp_s[m0 + 1];
        s4.z = sp_s[m0 + 2]; s4.w = sp_s[m0 + 3];
        o4.x = sp_o[m0 + 0]; o4.y = sp_o[m0 + 1];
        o4.z = sp_o[m0 + 2]; o4.w = sp_o[m0 + 3];

        float4 e = make_float4(0.f, 0.f, 0.f, 0.f);
#pragma unroll
        for (int j = 0; j < L; j++) {
            float4 xv = sm_tile[(ss * L + j) * MQP + mq];
            e.x = fmaf(o4.x, e.x, s4.x * xv.x);
            e.y = fmaf(o4.y, e.y, s4.y * xv.y);
            e.z = fmaf(o4.z, e.z, s4.z * xv.z);
            e.w = fmaf(o4.w, e.w, s4.w * xv.w);
        }
        sm_ep[ss * MQ + mq] = e;
    }
    __syncthreads();

    if (tid < MQ) {
        float4 dL = make_float4(1.f, 1.f, 1.f, 1.f);
#pragma unroll
        for (int k = 0; k < L; k++) {
            dL.x *= o4.x; dL.y *= o4.y; dL.z *= o4.z; dL.w *= o4.w;
        }
        // Exclusive combine: sm_ep[ss] := zero-init carry at subchunk start.
        float4 p = make_float4(0.f, 0.f, 0.f, 0.f);
#pragma unroll
        for (int k = 0; k < SS; k++) {
            float4 e = sm_ep[k * MQ + mq];
            sm_ep[k * MQ + mq] = p;
            p.x = fmaf(dL.x, p.x, e.x);
            p.y = fmaf(dL.y, p.y, e.y);
            p.z = fmaf(dL.z, p.z, e.z);
            p.w = fmaf(dL.w, p.w, e.w);
        }
    }
    __syncthreads();

    if (tid < SCAN_T) {
        int m0 = mq * 4;
        float4 na, d4, r4, dr4;
        na.x  = sp_na[m0 + 0]; na.y  = sp_na[m0 + 1];
        na.z  = sp_na[m0 + 2]; na.w  = sp_na[m0 + 3];
        d4.x  = sp_d[m0 + 0];  d4.y  = sp_d[m0 + 1];
        d4.z  = sp_d[m0 + 2];  d4.w  = sp_d[m0 + 3];
        r4.x  = sp_r[m0 + 0];  r4.y  = sp_r[m0 + 1];
        r4.z  = sp_r[m0 + 2];  r4.w  = sp_r[m0 + 3];
        dr4.x = sp_dr[m0 + 0]; dr4.y = sp_dr[m0 + 1];
        dr4.z = sp_dr[m0 + 2]; dr4.w = sp_dr[m0 + 3];

        float4 dL = make_float4(1.f, 1.f, 1.f, 1.f);
#pragma unroll
        for (int k = 0; k < L; k++) {
            dL.x *= o4.x; dL.y *= o4.y; dL.z *= o4.z; dL.w *= o4.w;
        }
        float4 f = make_float4(1.f, 1.f, 1.f, 1.f);
        for (int k = 0; k < ss; k++) {
            f.x *= dL.x; f.y *= dL.y; f.z *= dL.z; f.w *= dL.w;
        }

        float4 cb = __ldg(&g_carry[((size_t)c * B_ + b) * MQ + mq]);
        float4 m  = sm_ep[ss * MQ + mq];
        m.x = fmaf(f.x, cb.x, m.x);
        m.y = fmaf(f.y, cb.y, m.y);
        m.z = fmaf(f.z, cb.z, m.z);
        m.w = fmaf(f.w, cb.w, m.w);

        float4* op = out + ((size_t)b * T_ + (size_t)c * CL) * MQ;
#pragma unroll
        for (int j = 0; j < L; j++) {
            float4 xv = sm_tile[(ss * L + j) * MQP + mq];
            m.x = fmaf(o4.x, m.x, s4.x * xv.x);
            m.y = fmaf(o4.y, m.y, s4.y * xv.y);
            m.z = fmaf(o4.z, m.z, s4.z * xv.z);
            m.w = fmaf(o4.w, m.w, s4.w * xv.w);
            float4 ov;
            ov.x = pcen_out(xv.x, m.x, na.x, d4.x, r4.x, dr4.x);
            ov.y = pcen_out(xv.y, m.y, na.y, d4.y, r4.y, dr4.y);
            ov.z = pcen_out(xv.z, m.z, na.z, d4.z, r4.z, dr4.z);
            ov.w = pcen_out(xv.w, m.w, na.w, d4.w, r4.w, dr4.w);
            op[(ss * L + j) * MQ + mq] = ov;
        }
    }
}

extern "C" void kernel_launch(void* const* d_in, const int* in_sizes, int n_in,
                              void* d_out, int out_size) {
    const float* x         = (const float*)d_in[0];
    const float* log_s     = (const float*)d_in[1];
    const float* log_alpha = (const float*)d_in[2];
    const float* log_delta = (const float*)d_in[3];
    const float* log_r     = (const float*)d_in[4];
    float* out = (float*)d_out;

    pcen_pass1<<<NC * B_, NTH>>>((const float4*)x, log_s);
    pcen_pass2<<<SLANES / LPB, NTH>>>(log_s);
    pcen_pass3<<<NC * B_, NTH>>>(
        (const float4*)x, log_s, log_alpha, log_delta, log_r, (float4*)out);
}

// round 10
// speedup vs baseline: 1.2874x; 1.2874x over previous
#include <cuda_runtime.h>

#define EPS 1e-6f

static constexpr int B_ = 64;
static constexpr int T_ = 8000;
static constexpr int M_ = 80;
static constexpr int NC = 125;           // chunks over time
static constexpr int CL = T_ / NC;       // 64 steps per chunk
static constexpr int MQ = M_ / 4;        // 20 float4 lanes per row
static constexpr int LANES = B_ * MQ;    // 1280 float4 lanes
static constexpr int SLANES = B_ * M_;   // 5120 scalar lanes
static constexpr int NTH = NC * LANES;   // 160000 threads for pass1/pass3

// Scratch (no cudaMalloc allowed). Scalar view: [NC][B_*M_] floats.
__device__ float4 g_partial[NC * LANES];
__device__ float4 g_carry[NC * LANES];

// Single-instruction MUFU wrappers.
__device__ __forceinline__ float fast_lg2(float v) {
    float r; asm("lg2.approx.f32 %0, %1;" : "=f"(r) : "f"(v)); return r;
}
__device__ __forceinline__ float fast_ex2(float v) {
    float r; asm("ex2.approx.f32 %0, %1;" : "=f"(r) : "f"(v)); return r;
}

// ---------------------------------------------------------------------------
// Pass 1: each (chunk c, batch b, mel-quad mq) thread scans its chunk with
// m_init = 0, recording the chunk-local EMA endpoint. Pure strided streaming:
// consecutive threads hit consecutive float4 -> 512B/warp coalesced segments.
// ---------------------------------------------------------------------------
__global__ void __launch_bounds__(256) pcen_pass1(
        const float4* __restrict__ x, const float* __restrict__ log_s) {
    int tid = blockIdx.x * blockDim.x + threadIdx.x;
    if (tid >= NTH) return;
    int mq   = tid % MQ;
    int rest = tid / MQ;
    int b    = rest % B_;
    int c    = rest / B_;

    float s0 = __expf(log_s[mq * 4 + 0]);
    float s1 = __expf(log_s[mq * 4 + 1]);
    float s2 = __expf(log_s[mq * 4 + 2]);
    float s3 = __expf(log_s[mq * 4 + 3]);
    float o0 = 1.0f - s0, o1 = 1.0f - s1, o2 = 1.0f - s2, o3 = 1.0f - s3;

    const float4* xp = x + ((size_t)b * T_ + (size_t)c * CL) * MQ + mq;
    float4 mv = make_float4(0.f, 0.f, 0.f, 0.f);

#pragma unroll 16
    for (int j = 0; j < CL; j++) {
        float4 xv = __ldg(&xp[(size_t)j * MQ]);
        mv.x = fmaf(o0, mv.x, s0 * xv.x);
        mv.y = fmaf(o1, mv.y, s1 * xv.y);
        mv.z = fmaf(o2, mv.z, s2 * xv.z);
        mv.w = fmaf(o3, mv.w, s3 * xv.w);
    }
    g_partial[tid] = mv;
}

// ---------------------------------------------------------------------------
// Pass 2: per-lane serial combine of NC chunk carries, staged through SMEM.
//   carry_{c+1} = local_end_c + (1-s)^CL * carry_c
// (1-s)^CL as a literal 64-multiply product (matches serial rounding).
// ---------------------------------------------------------------------------
static constexpr int LPB = 64;   // scalar lanes per block
__global__ void __launch_bounds__(256) pcen_pass2(
        const float* __restrict__ log_s) {
    __shared__ float sm[NC][LPB];  // 32000 B
    const int lane0 = blockIdx.x * LPB;
    const float* gp = reinterpret_cast<const float*>(g_partial);
    float*       gc = reinterpret_cast<float*>(g_carry);

    for (int i = threadIdx.x; i < NC * LPB; i += blockDim.x) {
        int c = i / LPB, l = i % LPB;
        sm[c][l] = gp[(size_t)c * SLANES + lane0 + l];
    }
    __syncthreads();

    if (threadIdx.x < LPB) {
        int l = threadIdx.x;
        int m = (lane0 + l) % M_;
        float s   = __expf(log_s[m]);
        float oms = 1.0f - s;
        float dC  = 1.0f;
#pragma unroll
        for (int i = 0; i < CL; i++) dC *= oms;

        float carry = 0.0f;
#pragma unroll 5
        for (int c = 0; c < NC; c++) {
            float p = sm[c][l];
            sm[c][l] = carry;              // carry-IN for chunk c
            carry = fmaf(dC, carry, p);
        }
    }
    __syncthreads();

    for (int i = threadIdx.x; i < NC * LPB; i += blockDim.x) {
        int c = i / LPB, l = i % LPB;
        gc[(size_t)c * SLANES + lane0 + l] = sm[c][l];
    }
}

// ---------------------------------------------------------------------------
// Pass 3: rescan each chunk from its exact carry-in and emit output.
// out = ex2(r * lg2(fma(x, ex2(-alpha*lg2(m+eps)), delta))) - delta_r
// 4 MUFU ops per element; no division. m-chain serial; epilogue independent
// across unrolled steps -> ILP hides MUFU latency.
// ---------------------------------------------------------------------------
__device__ __forceinline__ float pcen_out(float xv, float mv, float nalpha,
                                          float delta, float r, float dr) {
    float l   = fast_lg2(mv + EPS);
    float den = fast_ex2(nalpha * l);
    float y   = fmaf(xv, den, delta);
    return fast_ex2(r * fast_lg2(y)) - dr;
}

__global__ void __launch_bounds__(256) pcen_pass3(
        const float4* __restrict__ x,
        const float* __restrict__ log_s,
        const float* __restrict__ log_alpha,
        const float* __restrict__ log_delta,
        const float* __restrict__ log_r,
        float4* __restrict__ out) {
    int tid = blockIdx.x * blockDim.x + threadIdx.x;
    if (tid >= NTH) return;
    int mq   = tid % MQ;
    int rest = tid / MQ;
    int b    = rest % B_;
    int c    = rest / B_;

    float s0, s1, s2, s3, o0, o1, o2, o3;
    float na0, na1, na2, na3;
    float d0, d1, d2, d3;
    float r0, r1, r2, r3;
    float dr0, dr1, dr2, dr3;
    {
        int m0 = mq * 4;
        s0 = __expf(log_s[m0 + 0]); s1 = __expf(log_s[m0 + 1]);
        s2 = __expf(log_s[m0 + 2]); s3 = __expf(log_s[m0 + 3]);
        o0 = 1.0f - s0; o1 = 1.0f - s1; o2 = 1.0f - s2; o3 = 1.0f - s3;
        na0 = -__expf(log_alpha[m0 + 0]); na1 = -__expf(log_alpha[m0 + 1]);
        na2 = -__expf(log_alpha[m0 + 2]); na3 = -__expf(log_alpha[m0 + 3]);
        d0 = __expf(log_delta[m0 + 0]); d1 = __expf(log_delta[m0 + 1]);
        d2 = __expf(log_delta[m0 + 2]); d3 = __expf(log_delta[m0 + 3]);
        r0 = __expf(log_r[m0 + 0]); r1 = __expf(log_r[m0 + 1]);
        r2 = __expf(log_r[m0 + 2]); r3 = __expf(log_r[m0 + 3]);
        dr0 = __expf(r0 * log_delta[m0 + 0]);
        dr1 = __expf(r1 * log_delta[m0 + 1]);
        dr2 = __expf(r2 * log_delta[m0 + 2]);
        dr3 = __expf(r3 * log_delta[m0 + 3]);
    }

    float4 mv = g_carry[tid];
    const float4* xp = x   + ((size_t)b * T_ + (size_t)c * CL) * MQ + mq;
    float4*       op = out + ((size_t)b * T_ + (size_t)c * CL) * MQ + mq;

#pragma unroll 8
    for (int j = 0; j < CL; j++) {
        float4 xv = __ldg(&xp[(size_t)j * MQ]);
        mv.x = fmaf(o0, mv.x, s0 * xv.x);
        mv.y = fmaf(o1, mv.y, s1 * xv.y);
        mv.z = fmaf(o2, mv.z, s2 * xv.z);
        mv.w = fmaf(o3, mv.w, s3 * xv.w);
        float4 ov;
        ov.x = pcen_out(xv.x, mv.x, na0, d0, r0, dr0);
        ov.y = pcen_out(xv.y, mv.y, na1, d1, r1, dr1);
        ov.z = pcen_out(xv.z, mv.z, na2, d2, r2, dr2);
        ov.w = pcen_out(xv.w, mv.w, na3, d3, r3, dr3);
        op[(size_t)j * MQ] = ov;
    }
}

extern "C" void kernel_launch(void* const* d_in, const int* in_sizes, int n_in,
                              void* d_out, int out_size) {
    const float* x         = (const float*)d_in[0];
    const float* log_s     = (const float*)d_in[1];
    const float* log_alpha = (const float*)d_in[2];
    const float* log_delta = (const float*)d_in[3];
    const float* log_r     = (const float*)d_in[4];
    float* out = (float*)d_out;

    const int threads = 256;
    pcen_pass1<<<(NTH + threads - 1) / threads, threads>>>(
        (const float4*)x, log_s);
    pcen_pass2<<<SLANES / LPB, threads>>>(log_s);
    pcen_pass3<<<(NTH + threads - 1) / threads, threads>>>(
        (const float4*)x, log_s, log_alpha, log_delta, log_r, (float4*)out);
}